// round 2
// baseline (speedup 1.0000x reference)
#include <cuda_runtime.h>

#define N_NODES  100000
#define N_EDGES  2000000
#define N_GRAPHS 1000
#define DIM      32
#define NF       7

// ---- device scratch (static; no allocations allowed); 16B-aligned for
// float4 loads and red.v4 stores ----
__device__ __align__(16) float d_h[N_NODES * DIM];     // node features (32-dim)
__device__ __align__(16) float d_agg[N_NODES * DIM];   // 32-dim scatter accumulator
__device__ __align__(16) float d_xp[N_NODES * 8];      // padded 8-dim input features
__device__ __align__(16) float d_aggx[N_NODES * 8];    // 8-dim scatter accumulator (layer 1)
__device__ __align__(16) float d_pool[N_GRAPHS * DIM]; // per-graph pooled features
__device__ __align__(16) int   d_src[N_EDGES];
__device__ __align__(16) int   d_dst[N_EDGES];

// ---------------------------------------------------------------------------
// Prep: split edge index (int32, shape [2, N_EDGES]) into src/dst
__global__ void prep_edges(const int* __restrict__ ei) {
    int i = blockIdx.x * blockDim.x + threadIdx.x;
    if (i < N_EDGES) {
        d_src[i] = ei[i];
        d_dst[i] = ei[N_EDGES + i];
    }
}

// Prep: pad x (100k x 7) -> xp (100k x 8), zero aggx, zero pool
__global__ void prep_x(const float* __restrict__ x) {
    int i = blockIdx.x * blockDim.x + threadIdx.x;
    if (i < N_NODES * 8) {
        int n = i >> 3, j = i & 7;
        d_xp[i]   = (j < NF) ? x[n * NF + j] : 0.0f;
        d_aggx[i] = 0.0f;
        if (i < N_GRAPHS * DIM) d_pool[i] = 0.0f;
    }
}

// ---------------------------------------------------------------------------
__device__ __forceinline__ void red_add_v4(float* a, float4 v) {
    asm volatile("red.global.add.v4.f32 [%0], {%1,%2,%3,%4};"
                 :: "l"(a), "f"(v.x), "f"(v.y), "f"(v.z), "f"(v.w)
                 : "memory");
}

// Layer-1 scatter: 8-dim padded features, 2 threads per edge
__global__ void scatter8() {
    int t = blockIdx.x * blockDim.x + threadIdx.x;
    if (t >= N_EDGES * 2) return;
    int e = t >> 1, p = t & 1;
    int s = d_src[e], d = d_dst[e];
    float4 v = *reinterpret_cast<const float4*>(&d_xp[s * 8 + p * 4]);
    red_add_v4(&d_aggx[d * 8 + p * 4], v);
}

// 32-dim scatter: 8 threads per edge (one coalesced 128B line per edge)
__global__ void scatter32() {
    int t = blockIdx.x * blockDim.x + threadIdx.x;
    if (t >= N_EDGES * 8) return;
    int e = t >> 3, p = t & 7;
    int s = d_src[e], d = d_dst[e];
    float4 v = *reinterpret_cast<const float4*>(&d_h[s * DIM + p * 4]);
    red_add_v4(&d_agg[d * DIM + p * 4], v);
}

// ---------------------------------------------------------------------------
// Layer 1 MLP: z = xp + aggx (8-dim) -> W1(7x32) relu -> W2(32x32) -> relu -> BN
// One warp per node; lane j owns output dim j. Also zeroes d_agg for layer 2.
__global__ void mlp1(const float* __restrict__ W1, const float* __restrict__ b1,
                     const float* __restrict__ W2, const float* __restrict__ b2,
                     const float* __restrict__ gamma, const float* __restrict__ beta,
                     const float* __restrict__ mean, const float* __restrict__ var) {
    __shared__ float W1s[NF * 32], W2s[32 * 32], b1s[32], b2s[32], scs[32], shs[32];
    int tid = threadIdx.x;
    for (int i = tid; i < NF * 32; i += blockDim.x) W1s[i] = W1[i];
    for (int i = tid; i < 32 * 32; i += blockDim.x) W2s[i] = W2[i];
    if (tid < 32) {
        b1s[tid] = b1[tid]; b2s[tid] = b2[tid];
        float sc = gamma[tid] * rsqrtf(var[tid] + 1e-5f);
        scs[tid] = sc;
        shs[tid] = beta[tid] - mean[tid] * sc;
    }
    __syncthreads();

    int warp = tid >> 5, j = tid & 31;
    int n = blockIdx.x * (blockDim.x >> 5) + warp;
    if (n >= N_NODES) return;

    float zj = (j < 8) ? (d_xp[n * 8 + j] + d_aggx[n * 8 + j]) : 0.0f;
    float acc = b1s[j];
#pragma unroll
    for (int k = 0; k < NF; k++)
        acc = fmaf(__shfl_sync(0xffffffffu, zj, k), W1s[k * 32 + j], acc);
    acc = fmaxf(acc, 0.0f);

    float acc2 = b2s[j];
#pragma unroll
    for (int k = 0; k < 32; k++)
        acc2 = fmaf(__shfl_sync(0xffffffffu, acc, k), W2s[k * 32 + j], acc2);
    acc2 = fmaxf(acc2, 0.0f);

    d_h[n * DIM + j]   = acc2 * scs[j] + shs[j];
    d_agg[n * DIM + j] = 0.0f;   // prepare accumulator for next scatter
}

// Layers 2..5 MLP: z = h + agg (32-dim); reads agg then re-zeroes it.
__global__ void mlp_layer(const float* __restrict__ W1, const float* __restrict__ b1,
                          const float* __restrict__ W2, const float* __restrict__ b2,
                          const float* __restrict__ gamma, const float* __restrict__ beta,
                          const float* __restrict__ mean, const float* __restrict__ var) {
    __shared__ float W1s[32 * 32], W2s[32 * 32], b1s[32], b2s[32], scs[32], shs[32];
    int tid = threadIdx.x;
    for (int i = tid; i < 32 * 32; i += blockDim.x) { W1s[i] = W1[i]; W2s[i] = W2[i]; }
    if (tid < 32) {
        b1s[tid] = b1[tid]; b2s[tid] = b2[tid];
        float sc = gamma[tid] * rsqrtf(var[tid] + 1e-5f);
        scs[tid] = sc;
        shs[tid] = beta[tid] - mean[tid] * sc;
    }
    __syncthreads();

    int warp = tid >> 5, j = tid & 31;
    int n = blockIdx.x * (blockDim.x >> 5) + warp;
    if (n >= N_NODES) return;

    float zj = d_h[n * DIM + j] + d_agg[n * DIM + j];
    d_agg[n * DIM + j] = 0.0f;   // reset for next layer's scatter

    float acc = b1s[j];
#pragma unroll
    for (int k = 0; k < 32; k++)
        acc = fmaf(__shfl_sync(0xffffffffu, zj, k), W1s[k * 32 + j], acc);
    acc = fmaxf(acc, 0.0f);

    float acc2 = b2s[j];
#pragma unroll
    for (int k = 0; k < 32; k++)
        acc2 = fmaf(__shfl_sync(0xffffffffu, acc, k), W2s[k * 32 + j], acc2);
    acc2 = fmaxf(acc2, 0.0f);

    d_h[n * DIM + j] = acc2 * scs[j] + shs[j];
}

// ---------------------------------------------------------------------------
// Global add pool: 8 threads per node, red.v4 into pool[batch[n]]
__global__ void pool_scatter(const int* __restrict__ batch) {
    int t = blockIdx.x * blockDim.x + threadIdx.x;
    if (t >= N_NODES * 8) return;
    int n = t >> 3, p = t & 7;
    int g = batch[n];
    float4 v = *reinterpret_cast<const float4*>(&d_h[n * DIM + p * 4]);
    red_add_v4(&d_pool[g * DIM + p * 4], v);
}

// Head: fc1 (32x32) + relu + fc2 (32x2) + log_softmax. One warp per graph.
__global__ void head(const float* __restrict__ fc1W, const float* __restrict__ fc1b,
                     const float* __restrict__ fc2W, const float* __restrict__ fc2b,
                     float* __restrict__ out) {
    __shared__ float W1s[32 * 32], W2s[64], b1s[32], b2s[2];
    int tid = threadIdx.x;
    for (int i = tid; i < 32 * 32; i += blockDim.x) W1s[i] = fc1W[i];
    if (tid < 64) W2s[tid] = fc2W[tid];
    if (tid < 32) b1s[tid] = fc1b[tid];
    if (tid < 2)  b2s[tid] = fc2b[tid];
    __syncthreads();

    int warp = tid >> 5, j = tid & 31;
    int g = blockIdx.x * (blockDim.x >> 5) + warp;
    if (g >= N_GRAPHS) return;

    float gj = d_pool[g * DIM + j];
    float a = b1s[j];
#pragma unroll
    for (int k = 0; k < 32; k++)
        a = fmaf(__shfl_sync(0xffffffffu, gj, k), W1s[k * 32 + j], a);
    a = fmaxf(a, 0.0f);

    float p0 = a * W2s[j * 2 + 0];
    float p1 = a * W2s[j * 2 + 1];
#pragma unroll
    for (int off = 16; off > 0; off >>= 1) {
        p0 += __shfl_down_sync(0xffffffffu, p0, off);
        p1 += __shfl_down_sync(0xffffffffu, p1, off);
    }
    if (j == 0) {
        float z0 = p0 + b2s[0];
        float z1 = p1 + b2s[1];
        float m = fmaxf(z0, z1);
        float lse = m + logf(expf(z0 - m) + expf(z1 - m));
        out[g * 2 + 0] = z0 - lse;
        out[g * 2 + 1] = z1 - lse;
    }
}

// ---------------------------------------------------------------------------
extern "C" void kernel_launch(void* const* d_in, const int* in_sizes, int n_in,
                              void* d_out, int out_size) {
    const float* x        = (const float*)d_in[0];
    const int*   ei       = (const int*)d_in[1];    // int32 (JAX x64 disabled)
    const int*   batch    = (const int*)d_in[2];    // int32
    const float* conv1_W1 = (const float*)d_in[3];
    const float* conv1_b1 = (const float*)d_in[4];
    const float* conv1_W2 = (const float*)d_in[5];
    const float* conv1_b2 = (const float*)d_in[6];
    const float* convs_W1 = (const float*)d_in[7];   // [4,32,32]
    const float* convs_b1 = (const float*)d_in[8];   // [4,32]
    const float* convs_W2 = (const float*)d_in[9];   // [4,32,32]
    const float* convs_b2 = (const float*)d_in[10];  // [4,32]
    const float* bn_gamma = (const float*)d_in[11];  // [5,32]
    const float* bn_beta  = (const float*)d_in[12];
    const float* bn_mean  = (const float*)d_in[13];
    const float* bn_var   = (const float*)d_in[14];
    const float* fc1_W    = (const float*)d_in[15];
    const float* fc1_b    = (const float*)d_in[16];
    const float* fc2_W    = (const float*)d_in[17];
    const float* fc2_b    = (const float*)d_in[18];
    float* out = (float*)d_out;

    prep_edges<<<(N_EDGES + 255) / 256, 256>>>(ei);
    prep_x<<<(N_NODES * 8 + 255) / 256, 256>>>(x);

    // Layer 1 (7-dim input, padded to 8)
    scatter8<<<(N_EDGES * 2 + 255) / 256, 256>>>();
    mlp1<<<(N_NODES + 7) / 8, 256>>>(conv1_W1, conv1_b1, conv1_W2, conv1_b2,
                                     bn_gamma, bn_beta, bn_mean, bn_var);

    // Layers 2..5
    for (int i = 0; i < 4; i++) {
        scatter32<<<(N_EDGES * 8 + 255) / 256, 256>>>();
        mlp_layer<<<(N_NODES + 7) / 8, 256>>>(
            convs_W1 + i * 32 * 32, convs_b1 + i * 32,
            convs_W2 + i * 32 * 32, convs_b2 + i * 32,
            bn_gamma + (i + 1) * 32, bn_beta + (i + 1) * 32,
            bn_mean + (i + 1) * 32,  bn_var + (i + 1) * 32);
    }

    // Pool + head
    pool_scatter<<<(N_NODES * 8 + 255) / 256, 256>>>(batch);
    head<<<(N_GRAPHS + 7) / 8, 256>>>(fc1_W, fc1_b, fc2_W, fc2_b, out);
}